// round 1
// baseline (speedup 1.0000x reference)
#include <cuda_runtime.h>
#include <cuda_bf16.h>

#define B_ROWS      131072
#define XSTRIDE     512            // S*D floats per batch row
#define THREADS     256
#define ROWS_PER_BLOCK 1024
#define NBLK        (B_ROWS / ROWS_PER_BLOCK)   // 128
#define NWARPS      (THREADS / 32)              // 8
#define ROWS_PER_WARP (ROWS_PER_BLOCK / NWARPS) // 128

__device__ float g_agg_y[NBLK];
__device__ float g_agg_p[NBLK];
__device__ float g_carry[NBLK];

// ---------------------------------------------------------------------------
// Pass 1: per-block dot products + local linear-recurrence scan.
// ---------------------------------------------------------------------------
__global__ void __launch_bounds__(THREADS, 1)
pass1_kernel(const float* __restrict__ x,
             const float* __restrict__ weight,
             const float* __restrict__ weight_h,
             const float* __restrict__ bias,
             float* __restrict__ out)
{
    __shared__ float s_u[ROWS_PER_BLOCK];
    __shared__ float s_wy[NWARPS];
    __shared__ float s_wp[NWARPS];

    const int tid  = threadIdx.x;
    const int wid  = tid >> 5;
    const int lane = tid & 31;

    const float w = weight_h[0];
    const float b = bias[0];

    // Each lane owns 4 consecutive weight elements (D=128 = 32 lanes * float4)
    const float4 wv = reinterpret_cast<const float4*>(weight)[lane];

    const int rowBase = blockIdx.x * ROWS_PER_BLOCK + wid * ROWS_PER_WARP;

    #pragma unroll 4
    for (int r = 0; r < ROWS_PER_WARP; r++) {
        const int row = rowBase + r;
        const float4 xv =
            reinterpret_cast<const float4*>(x + (size_t)row * XSTRIDE)[lane];
        float s = xv.x * wv.x + xv.y * wv.y + xv.z * wv.z + xv.w * wv.w;
        s += __shfl_xor_sync(0xFFFFFFFFu, s, 16);
        s += __shfl_xor_sync(0xFFFFFFFFu, s, 8);
        s += __shfl_xor_sync(0xFFFFFFFFu, s, 4);
        s += __shfl_xor_sync(0xFFFFFFFFu, s, 2);
        s += __shfl_xor_sync(0xFFFFFFFFu, s, 1);
        if (lane == 0) s_u[wid * ROWS_PER_WARP + r] = s + b;
    }
    __syncthreads();

    // ---- Thread-local scan over 4 consecutive elements ----
    const float u0 = s_u[4 * tid + 0];
    const float u1 = s_u[4 * tid + 1];
    const float u2 = s_u[4 * tid + 2];
    const float u3 = s_u[4 * tid + 3];

    const float y0 = u0;
    const float y1 = fmaf(w, y0, u1);
    const float y2 = fmaf(w, y1, u2);
    const float y3 = fmaf(w, y2, u3);

    const float w2 = w * w;
    const float w3 = w2 * w;
    const float w4 = w2 * w2;

    // ---- Warp inclusive scan of (Y, P) pairs ----
    float Y = y3, P = w4;
    #pragma unroll
    for (int d = 1; d < 32; d <<= 1) {
        const float Yp = __shfl_up_sync(0xFFFFFFFFu, Y, d);
        const float Pp = __shfl_up_sync(0xFFFFFFFFu, P, d);
        if (lane >= d) { Y = fmaf(P, Yp, Y); P *= Pp; }
    }
    if (lane == 31) { s_wy[wid] = Y; s_wp[wid] = P; }
    __syncthreads();

    // ---- Exclusive prefix over earlier warps (serial over <=7 entries) ----
    float Ew = 0.0f, Pw = 1.0f;
    #pragma unroll
    for (int k = 0; k < NWARPS; k++) {
        if (k < wid) { Ew = fmaf(s_wp[k], Ew, s_wy[k]); Pw *= s_wp[k]; }
    }

    // ---- Exclusive prefix within warp, then compose ----
    float Ye = __shfl_up_sync(0xFFFFFFFFu, Y, 1);
    float Pe = __shfl_up_sync(0xFFFFFFFFu, P, 1);
    if (lane == 0) { Ye = 0.0f; Pe = 1.0f; }
    const float Ex = fmaf(Pe, Ew, Ye);   // carry into this thread's segment

    // ---- Final values for this thread's 4 elements ----
    float4 ov;
    ov.x = fmaf(w,  Ex, y0);
    ov.y = fmaf(w2, Ex, y1);
    ov.z = fmaf(w3, Ex, y2);
    ov.w = fmaf(w4, Ex, y3);
    reinterpret_cast<float4*>(out + (size_t)blockIdx.x * ROWS_PER_BLOCK)[tid] = ov;

    // ---- Block aggregate (last thread holds full-block inclusive pair) ----
    if (tid == THREADS - 1) {
        g_agg_y[blockIdx.x] = ov.w;      // inclusive Y over all 1024 rows
        g_agg_p[blockIdx.x] = Pw * P;    // w^1024 (may underflow to 0: fine)
    }
}

// ---------------------------------------------------------------------------
// Pass 2: scan block aggregates -> exclusive carries; write y_last.
// ---------------------------------------------------------------------------
__global__ void pass2_kernel(float* __restrict__ out)
{
    __shared__ float sy[NBLK];
    __shared__ float sp[NBLK];
    const int tid = threadIdx.x;
    if (tid < NBLK) { sy[tid] = g_agg_y[tid]; sp[tid] = g_agg_p[tid]; }
    __syncthreads();
    if (tid == 0) {
        float C = 0.0f;
        #pragma unroll 8
        for (int k = 0; k < NBLK; k++) {
            g_carry[k] = C;
            C = fmaf(sp[k], C, sy[k]);
        }
        out[B_ROWS]     = C;   // y_h
        out[B_ROWS + 1] = C;   // y_h (duplicated output)
    }
}

// ---------------------------------------------------------------------------
// Pass 3: apply carries: out[j] += carry[blk] * w^(local+1)
// ---------------------------------------------------------------------------
__global__ void __launch_bounds__(THREADS, 1)
pass3_kernel(float* __restrict__ out, const float* __restrict__ weight_h)
{
    const float C = g_carry[blockIdx.x];
    if (C == 0.0f) return;               // uniform per block; block 0 always skips

    const float w = weight_h[0];
    const int tid = threadIdx.x;

    // w^(4*tid + 1) via binary exponentiation (exact-multiply chain, ~10 muls)
    unsigned k = 4u * tid + 1u;
    float p = 1.0f, base = w;
    while (k) {
        if (k & 1u) p *= base;
        base *= base;
        k >>= 1;
    }

    float4* o = reinterpret_cast<float4*>(out + (size_t)blockIdx.x * ROWS_PER_BLOCK) + tid;
    float4 v = *o;
    v.x = fmaf(C, p, v.x); p *= w;
    v.y = fmaf(C, p, v.y); p *= w;
    v.z = fmaf(C, p, v.z); p *= w;
    v.w = fmaf(C, p, v.w);
    *o = v;
}

// ---------------------------------------------------------------------------
extern "C" void kernel_launch(void* const* d_in, const int* in_sizes, int n_in,
                              void* d_out, int out_size)
{
    const float* x        = (const float*)d_in[0];
    const float* weight   = (const float*)d_in[1];
    const float* weight_h = (const float*)d_in[2];
    const float* bias     = (const float*)d_in[3];
    float* out            = (float*)d_out;

    pass1_kernel<<<NBLK, THREADS>>>(x, weight, weight_h, bias, out);
    pass2_kernel<<<1, NBLK>>>(out);
    pass3_kernel<<<NBLK, THREADS>>>(out, weight_h);
}

// round 5
// speedup vs baseline: 1.4168x; 1.4168x over previous
#include <cuda_runtime.h>
#include <cuda_bf16.h>

#define B_ROWS          131072
#define XSTRIDE         512                       // S*D floats per batch row
#define THREADS         256
#define ROWS_PER_BLOCK  256
#define NBLK            (B_ROWS / ROWS_PER_BLOCK) // 512
#define NWARPS          (THREADS / 32)            // 8
#define ROWS_PER_WARP   (ROWS_PER_BLOCK / NWARPS) // 32
#define BATCH           8                         // loads in flight per warp
#define LOOKBACK_W      8                         // aggregates read per round

__device__ float g_aggY[NBLK];
__device__ float g_aggP[NBLK];
__device__ int   g_flag[NBLK];

// ---------------------------------------------------------------------------
// Reset: zero the publish flags (must run before main kernel on every call).
// ---------------------------------------------------------------------------
__global__ void reset_kernel()
{
    g_flag[threadIdx.x] = 0;     // launched with NBLK threads
}

// ---------------------------------------------------------------------------
// Fused kernel: dot products + block scan + decoupled-lookback carry + write.
// ---------------------------------------------------------------------------
__global__ void __launch_bounds__(THREADS, 4)
fused_kernel(const float* __restrict__ x,
             const float* __restrict__ weight,
             const float* __restrict__ weight_h,
             const float* __restrict__ bias,
             float* __restrict__ out)
{
    __shared__ float s_u[ROWS_PER_BLOCK];
    __shared__ float s_wy[NWARPS];
    __shared__ float s_wp[NWARPS];
    __shared__ float s_C;

    const int tid  = threadIdx.x;
    const int wid  = tid >> 5;
    const int lane = tid & 31;
    const int blk  = blockIdx.x;

    const float w = weight_h[0];
    const float b = bias[0];

    // Each lane owns 4 consecutive weight elements (D=128 = 32 lanes * float4)
    const float4 wv = reinterpret_cast<const float4*>(weight)[lane];

    const int rowBase = blk * ROWS_PER_BLOCK + wid * ROWS_PER_WARP;

    // ---- Dot products: issue BATCH independent LDG.128 before reducing ----
    #pragma unroll
    for (int rr = 0; rr < ROWS_PER_WARP; rr += BATCH) {
        float4 xv[BATCH];
        #pragma unroll
        for (int j = 0; j < BATCH; j++) {
            xv[j] = reinterpret_cast<const float4*>(
                        x + (size_t)(rowBase + rr + j) * XSTRIDE)[lane];
        }
        #pragma unroll
        for (int j = 0; j < BATCH; j++) {
            float s = xv[j].x * wv.x + xv[j].y * wv.y
                    + xv[j].z * wv.z + xv[j].w * wv.w;
            s += __shfl_xor_sync(0xFFFFFFFFu, s, 16);
            s += __shfl_xor_sync(0xFFFFFFFFu, s, 8);
            s += __shfl_xor_sync(0xFFFFFFFFu, s, 4);
            s += __shfl_xor_sync(0xFFFFFFFFu, s, 2);
            s += __shfl_xor_sync(0xFFFFFFFFu, s, 1);
            if (lane == 0) s_u[wid * ROWS_PER_WARP + rr + j] = s + b;
        }
    }
    __syncthreads();

    // ---- Block-local linear-recurrence scan: thread tid owns element tid ----
    const float u = s_u[tid];

    float Y = u, P = w;
    #pragma unroll
    for (int d = 1; d < 32; d <<= 1) {
        const float Yp = __shfl_up_sync(0xFFFFFFFFu, Y, d);
        const float Pp = __shfl_up_sync(0xFFFFFFFFu, P, d);
        if (lane >= d) { Y = fmaf(P, Yp, Y); P *= Pp; }
    }
    if (lane == 31) { s_wy[wid] = Y; s_wp[wid] = P; }
    __syncthreads();

    // Exclusive prefix over earlier warps (serial over <=7 entries)
    float Ew = 0.0f, Pw = 1.0f;
    #pragma unroll
    for (int k = 0; k < NWARPS; k++) {
        if (k < wid) { Ew = fmaf(s_wp[k], Ew, s_wy[k]); Pw *= s_wp[k]; }
    }

    // Block-local inclusive value for this element
    const float yv = fmaf(P, Ew, Y);

    // ---- Publish this block's aggregate (Y_blk, P_blk = w^256) ----
    if (tid == THREADS - 1) {
        g_aggY[blk] = yv;
        g_aggP[blk] = Pw * P;            // w^256 (typically underflows to 0)
        __threadfence();
        atomicExch(&g_flag[blk], 1);
    }

    // ---- w^(tid+1) via binary exponentiation (overlaps lookback wait) ----
    unsigned e = (unsigned)tid + 1u;
    float powv = 1.0f, base = w;
    while (e) {
        if (e & 1u) powv *= base;
        base *= base;
        e >>= 1;
    }

    // ---- Decoupled lookback: compose predecessor aggregates (deterministic,
    //      fixed order; terminates when multiplier hits exact 0) ----
    if (tid == 0) {
        float C = 0.0f;
        if (blk > 0) {
            volatile int*   vf = g_flag;
            volatile float* vy = g_aggY;
            volatile float* vp = g_aggP;
            float M = 1.0f;
            int k = blk - 1;
            while (k >= 0 && M != 0.0f) {
                const int n = (k + 1 < LOOKBACK_W) ? (k + 1) : LOOKBACK_W;
                // wait until all n predecessor aggregates are published
                bool ready;
                do {
                    ready = true;
                    #pragma unroll
                    for (int j = 0; j < LOOKBACK_W; j++)
                        if (j < n && vf[k - j] == 0) ready = false;
                } while (!ready);
                float Ys[LOOKBACK_W], Ps[LOOKBACK_W];
                #pragma unroll
                for (int j = 0; j < LOOKBACK_W; j++) {
                    if (j < n) { Ys[j] = vy[k - j]; Ps[j] = vp[k - j]; }
                }
                #pragma unroll
                for (int j = 0; j < LOOKBACK_W; j++) {
                    if (j < n && M != 0.0f) {
                        C = fmaf(M, Ys[j], C);
                        M *= Ps[j];
                    }
                }
                k -= n;
            }
        }
        s_C = C;
    }
    __syncthreads();

    // ---- Final value and single write of the output ----
    const float C = s_C;
    const float fin = fmaf(C, powv, yv);
    out[(size_t)blk * ROWS_PER_BLOCK + tid] = fin;

    if (blk == NBLK - 1 && tid == THREADS - 1) {
        out[B_ROWS]     = fin;   // y_h
        out[B_ROWS + 1] = fin;   // y_h (duplicated output)
    }
}

// ---------------------------------------------------------------------------
extern "C" void kernel_launch(void* const* d_in, const int* in_sizes, int n_in,
                              void* d_out, int out_size)
{
    const float* x        = (const float*)d_in[0];
    const float* weight   = (const float*)d_in[1];
    const float* weight_h = (const float*)d_in[2];
    const float* bias     = (const float*)d_in[3];
    float* out            = (float*)d_out;

    reset_kernel<<<1, NBLK>>>();
    fused_kernel<<<NBLK, THREADS>>>(x, weight, weight_h, bias, out);
}

// round 10
// speedup vs baseline: 1.6441x; 1.1604x over previous
#include <cuda_runtime.h>
#include <cuda_bf16.h>

#define B_ROWS          131072
#define XSTRIDE         512                       // S*D floats per batch row
#define THREADS         128
#define ROWS_PER_BLOCK  128
#define NBLK            (B_ROWS / ROWS_PER_BLOCK) // 1024
#define NWARPS          (THREADS / 32)            // 4
#define ROWS_PER_WARP   (ROWS_PER_BLOCK / NWARPS) // 32
#define LOOKBACK_W      8                         // aggregates read per round

__device__ float g_aggY[NBLK];
__device__ float g_aggP[NBLK];
__device__ int   g_flag[NBLK];   // generation counter; zero-init at load

// ---------------------------------------------------------------------------
// Fused kernel: dot products (octet-per-row, 8 loads in flight) + block scan
//   + decoupled-lookback carry (generation-counter flags, no reset launch)
//   + single output write.
// ---------------------------------------------------------------------------
__global__ void __launch_bounds__(THREADS, 8)
fused_kernel(const float* __restrict__ x,
             const float* __restrict__ weight,
             const float* __restrict__ weight_h,
             const float* __restrict__ bias,
             float* __restrict__ out)
{
    __shared__ float s_u[ROWS_PER_BLOCK];
    __shared__ float s_wy[NWARPS];
    __shared__ float s_wp[NWARPS];
    __shared__ float s_C;

    const int tid   = threadIdx.x;
    const int wid   = tid >> 5;
    const int lane  = tid & 31;
    const int sub   = lane & 7;    // position within octet
    const int rquad = lane >> 3;   // which of 4 rows in the tile
    const int blk   = blockIdx.x;

    // Generation for this launch: own flag is only ever written by this block,
    // and every launch leaves all flags at the same value, so flag[blk] is the
    // globally consistent previous generation. Target = prev + 1.
    const int genTarget = *((volatile int*)&g_flag[blk]) + 1;

    const float w = weight_h[0];
    const float b = bias[0];

    // Each lane holds the 4 weight chunks its octet-position covers:
    // wc[i] = weight[ (i*8+sub)*4 .. +4 )   (i = 0..3 spans all 128 floats)
    const float4* w4 = reinterpret_cast<const float4*>(weight);
    float4 wc[4];
    #pragma unroll
    for (int i = 0; i < 4; i++) wc[i] = w4[i * 8 + sub];

    const int rowBase = blk * ROWS_PER_BLOCK + wid * ROWS_PER_WARP;

    // ---- Dot products: 8 tiles of 4 rows; 2 tiles (8 LDG.128) per batch ----
    #pragma unroll
    for (int t = 0; t < 8; t += 2) {
        const float4* rowA = reinterpret_cast<const float4*>(
            x + (size_t)(rowBase + t * 4 + rquad) * XSTRIDE);
        const float4* rowB = reinterpret_cast<const float4*>(
            x + (size_t)(rowBase + t * 4 + 4 + rquad) * XSTRIDE);

        float4 xa[4], xb[4];
        #pragma unroll
        for (int i = 0; i < 4; i++) xa[i] = rowA[i * 8 + sub];
        #pragma unroll
        for (int i = 0; i < 4; i++) xb[i] = rowB[i * 8 + sub];

        float sA = 0.0f, sB = 0.0f;
        #pragma unroll
        for (int i = 0; i < 4; i++) {
            sA = fmaf(xa[i].x, wc[i].x, sA); sA = fmaf(xa[i].y, wc[i].y, sA);
            sA = fmaf(xa[i].z, wc[i].z, sA); sA = fmaf(xa[i].w, wc[i].w, sA);
            sB = fmaf(xb[i].x, wc[i].x, sB); sB = fmaf(xb[i].y, wc[i].y, sB);
            sB = fmaf(xb[i].z, wc[i].z, sB); sB = fmaf(xb[i].w, wc[i].w, sB);
        }
        // Octet reduce (3 shfl): result lands on sub==0 of each octet
        sA += __shfl_xor_sync(0xFFFFFFFFu, sA, 4);
        sB += __shfl_xor_sync(0xFFFFFFFFu, sB, 4);
        sA += __shfl_xor_sync(0xFFFFFFFFu, sA, 2);
        sB += __shfl_xor_sync(0xFFFFFFFFu, sB, 2);
        sA += __shfl_xor_sync(0xFFFFFFFFu, sA, 1);
        sB += __shfl_xor_sync(0xFFFFFFFFu, sB, 1);
        if (sub == 0) {
            s_u[wid * ROWS_PER_WARP + t * 4 + rquad]     = sA + b;
            s_u[wid * ROWS_PER_WARP + t * 4 + 4 + rquad] = sB + b;
        }
    }
    __syncthreads();

    // ---- Block-local linear-recurrence scan: thread tid owns element tid ----
    const float u = s_u[tid];

    float Y = u, P = w;
    #pragma unroll
    for (int d = 1; d < 32; d <<= 1) {
        const float Yp = __shfl_up_sync(0xFFFFFFFFu, Y, d);
        const float Pp = __shfl_up_sync(0xFFFFFFFFu, P, d);
        if (lane >= d) { Y = fmaf(P, Yp, Y); P *= Pp; }
    }
    if (lane == 31) { s_wy[wid] = Y; s_wp[wid] = P; }
    __syncthreads();

    // Exclusive prefix over earlier warps (serial over <=3 entries)
    float Ew = 0.0f, Pw = 1.0f;
    #pragma unroll
    for (int k = 0; k < NWARPS; k++) {
        if (k < wid) { Ew = fmaf(s_wp[k], Ew, s_wy[k]); Pw *= s_wp[k]; }
    }

    // Block-local inclusive value for this element
    const float yv = fmaf(P, Ew, Y);

    // ---- Publish this block's aggregate (Y_blk, P_blk = w^128) ----
    if (tid == THREADS - 1) {
        g_aggY[blk] = yv;
        g_aggP[blk] = Pw * P;            // w^128
        __threadfence();
        atomicExch(&g_flag[blk], genTarget);
    }

    // ---- w^(tid+1) via binary exponentiation (overlaps lookback wait) ----
    unsigned e = (unsigned)tid + 1u;
    float powv = 1.0f, base = w;
    while (e) {
        if (e & 1u) powv *= base;
        base *= base;
        e >>= 1;
    }

    // ---- Decoupled lookback: compose predecessor aggregates (deterministic,
    //      fixed order; terminates when multiplier hits exact 0) ----
    if (tid == 0) {
        float C = 0.0f;
        if (blk > 0) {
            volatile int*   vf = g_flag;
            volatile float* vy = g_aggY;
            volatile float* vp = g_aggP;
            float M = 1.0f;
            int k = blk - 1;
            while (k >= 0 && M != 0.0f) {
                const int n = (k + 1 < LOOKBACK_W) ? (k + 1) : LOOKBACK_W;
                bool ready;
                do {
                    ready = true;
                    #pragma unroll
                    for (int j = 0; j < LOOKBACK_W; j++)
                        if (j < n && vf[k - j] != genTarget) ready = false;
                } while (!ready);
                float Ys[LOOKBACK_W], Ps[LOOKBACK_W];
                #pragma unroll
                for (int j = 0; j < LOOKBACK_W; j++) {
                    if (j < n) { Ys[j] = vy[k - j]; Ps[j] = vp[k - j]; }
                }
                #pragma unroll
                for (int j = 0; j < LOOKBACK_W; j++) {
                    if (j < n && M != 0.0f) {
                        C = fmaf(M, Ys[j], C);
                        M *= Ps[j];
                    }
                }
                k -= n;
            }
        }
        s_C = C;
    }
    __syncthreads();

    // ---- Final value and single write of the output ----
    const float C = s_C;
    const float fin = fmaf(C, powv, yv);
    out[(size_t)blk * ROWS_PER_BLOCK + tid] = fin;

    if (blk == NBLK - 1 && tid == THREADS - 1) {
        out[B_ROWS]     = fin;   // y_h
        out[B_ROWS + 1] = fin;   // y_h (duplicated output)
    }
}

// ---------------------------------------------------------------------------
extern "C" void kernel_launch(void* const* d_in, const int* in_sizes, int n_in,
                              void* d_out, int out_size)
{
    const float* x        = (const float*)d_in[0];
    const float* weight   = (const float*)d_in[1];
    const float* weight_h = (const float*)d_in[2];
    const float* bias     = (const float*)d_in[3];
    float* out            = (float*)d_out;

    fused_kernel<<<NBLK, THREADS>>>(x, weight, weight_h, bias, out);
}